// round 3
// baseline (speedup 1.0000x reference)
#include <cuda_runtime.h>
#include <cuda_fp16.h>
#include <math.h>

#define BB 64
#define TT 512
#define NN 256
#define DD 128
#define LOG_2PI_F 1.8378770664093453f

// ---------------- device scratch (static globals; no allocs) ----------------
static __device__ float   E_sc[BB * TT * NN];          // emission logprobs [B*T, N] fp32 (33.5 MB)
static __device__ float   Aexp_sc[NN * NN];            // softmax(transition) rows, fp32
static __device__ __half2 AhT_g[(NN / 2) * NN];        // packed A^T: [k][j] = (A[2k][j], A[2k+1][j])
static __device__ __half2 WpT_g[DD * NN];              // [d][n] = (-0.5*iv, mu*iv) as half2
static __device__ float   cvec_g[NN];                  // -0.5 * sum_d (mu^2*iv + log_var + LOG2PI)
static __device__ float   logpi_g[NN];
static __device__ float   logprop_g[BB];

// ---------------- prep: log_softmax of state priors ----------------
__global__ void prep_pi(const float* __restrict__ pri) {
    __shared__ float red[8];
    int j = threadIdx.x, wid = j >> 5, lane = j & 31;
    float v = pri[j];
    float m = v;
#pragma unroll
    for (int o = 16; o; o >>= 1) m = fmaxf(m, __shfl_xor_sync(0xffffffffu, m, o));
    if (lane == 0) red[wid] = m;
    __syncthreads();
    float mb = red[0];
#pragma unroll
    for (int w = 1; w < 8; w++) mb = fmaxf(mb, red[w]);
    __syncthreads();
    float e = expf(v - mb);
    float s = e;
#pragma unroll
    for (int o = 16; o; o >>= 1) s += __shfl_xor_sync(0xffffffffu, s, o);
    if (lane == 0) red[wid] = s;
    __syncthreads();
    float sb = 0.f;
#pragma unroll
    for (int w = 0; w < 8; w++) sb += red[w];
    logpi_g[j] = (v - mb) - logf(sb);
}

// ---------------- prep: row softmax of transition matrix -> Aexp ----------------
__global__ void prep_trans(const float* __restrict__ trans) {
    __shared__ float red[8];
    int i = blockIdx.x, j = threadIdx.x, wid = j >> 5, lane = j & 31;
    float v = trans[i * NN + j];
    float m = v;
#pragma unroll
    for (int o = 16; o; o >>= 1) m = fmaxf(m, __shfl_xor_sync(0xffffffffu, m, o));
    if (lane == 0) red[wid] = m;
    __syncthreads();
    float mb = red[0];
#pragma unroll
    for (int w = 1; w < 8; w++) mb = fmaxf(mb, red[w]);
    __syncthreads();
    float e = expf(v - mb);
    float s = e;
#pragma unroll
    for (int o = 16; o; o >>= 1) s += __shfl_xor_sync(0xffffffffu, s, o);
    if (lane == 0) red[wid] = s;
    __syncthreads();
    float sb = 0.f;
#pragma unroll
    for (int w = 0; w < 8; w++) sb += red[w];
    Aexp_sc[i * NN + j] = e / sb;
}

// ---------------- prep: pack A transposed into half2 pairs, k-major ----------------
// AhT_g[k*NN + j] = (A[2k][j], A[2k+1][j]); reads and writes coalesced over j.
__global__ void prep_packA() {
    int k = blockIdx.x;         // 0..127
    int j = threadIdx.x;        // 0..255
    float a0 = Aexp_sc[(2 * k) * NN + j];
    float a1 = Aexp_sc[(2 * k + 1) * NN + j];
    AhT_g[k * NN + j] = __floats2half2_rn(a0, a1);
}

// ---------------- prep: emission weights packed ----------------
__global__ void prep_W(const float* __restrict__ mu, const float* __restrict__ lv) {
    int idx = blockIdx.x * blockDim.x + threadIdx.x;   // 0..32767
    int n = idx >> 7, d = idx & 127;
    float l = lv[idx];
    float iv = expf(-l);
    float w1 = -0.5f * iv;
    float w2 = mu[idx] * iv;
    WpT_g[d * NN + n] = __floats2half2_rn(w1, w2);
}

// ---------------- prep: per-state constant ----------------
__global__ void prep_c(const float* __restrict__ mu, const float* __restrict__ lv) {
    __shared__ float red[4];
    int n = blockIdx.x, d = threadIdx.x, wid = d >> 5, lane = d & 31;
    float l = lv[n * DD + d];
    float m = mu[n * DD + d];
    float iv = expf(-l);
    float t = m * m * iv + l + LOG_2PI_F;
#pragma unroll
    for (int o = 16; o; o >>= 1) t += __shfl_xor_sync(0xffffffffu, t, o);
    if (lane == 0) red[wid] = t;
    __syncthreads();
    if (d == 0) {
        float s = red[0] + red[1] + red[2] + red[3];
        cvec_g[n] = -0.5f * s;
    }
}

// ---------------- emission GEMM: E[m,n] = sum_d (x^2*w1 + x*w2) + c[n] ----------------
// Grid: 1024 CTAs x 256 threads. CTA handles 32 rows x all 256 states.
// Thread n keeps its weight column in 128 half2 registers; X tile broadcast from smem.
__global__ void __launch_bounds__(256, 1) emis_kernel(const float* __restrict__ X) {
    __shared__ __align__(16) __half2 xp[32 * DD];      // (x^2, x) pairs, [m][d], 16 KB
    int tid = threadIdx.x;
    int r0 = blockIdx.x * 32;

    // load X tile, square-pack
#pragma unroll
    for (int it = 0; it < 16; it++) {
        int idx = it * 256 + tid;                      // 0..4095, coalesced over d
        int m = idx >> 7, d = idx & 127;
        float x = X[(r0 + m) * DD + d];
        xp[idx] = __floats2half2_rn(x * x, x);
    }

    int n = tid;
    __half2 w[DD];
#pragma unroll
    for (int dd = 0; dd < DD; dd++) w[dd] = WpT_g[dd * NN + n];   // coalesced over n
    float cn = cvec_g[n];
    __syncthreads();

    for (int m = 0; m < 32; m++) {
        const float4* xr = reinterpret_cast<const float4*>(&xp[m * DD]);
        __half2 a0 = __float2half2_rn(0.f), a1 = a0, a2 = a0, a3 = a0;
#pragma unroll
        for (int q = 0; q < 32; q++) {
            float4 v = xr[q];                          // broadcast LDS.128 (4 half2)
            const __half2* xv = reinterpret_cast<const __half2*>(&v);
            a0 = __hfma2(w[4 * q + 0], xv[0], a0);
            a1 = __hfma2(w[4 * q + 1], xv[1], a1);
            a2 = __hfma2(w[4 * q + 2], xv[2], a2);
            a3 = __hfma2(w[4 * q + 3], xv[3], a3);
        }
        float2 f0 = __half22float2(a0), f1 = __half22float2(a1);
        float2 f2 = __half22float2(a2), f3 = __half22float2(a3);
        float s = ((f0.x + f0.y) + (f1.x + f1.y)) + ((f2.x + f2.y) + (f3.x + f3.y)) + cn;
        E_sc[(r0 + m) * NN + n] = s;                   // coalesced over n
    }
}

// ---------------- forward recursion: 1 CTA per batch element ----------------
// Thread j holds A column j (128 half2) in registers. Per step:
//   S_j = sum_i p_i * A[i][j]  (HFMA2)
//   na_j = E[b,t,j] + m_prev + log(S_j); m_new = block max; p_j = exp(na_j - m_new)
__global__ void __launch_bounds__(256, 1) forward_rec() {
    __shared__ __align__(16) __half psm[NN];
    __shared__ float red[8];
    int b = blockIdx.x, j = threadIdx.x;
    int wid = j >> 5, lane = j & 31;

    __half2 a[DD];
#pragma unroll
    for (int k = 0; k < DD; k++) a[k] = AhT_g[k * NN + j];   // coalesced over j

    const float* __restrict__ Erow = E_sc + b * TT * NN;

    // alpha0
    float alpha = logpi_g[j] + Erow[j];
    float m = alpha;
#pragma unroll
    for (int o = 16; o; o >>= 1) m = fmaxf(m, __shfl_xor_sync(0xffffffffu, m, o));
    if (lane == 0) red[wid] = m;
    __syncthreads();
    float mb = red[0];
#pragma unroll
    for (int w = 1; w < 8; w++) mb = fmaxf(mb, red[w]);
    float p = __expf(alpha - mb);
    psm[j] = __float2half(p);
    float mprev = mb;
    float e_next = Erow[1 * NN + j];
    __syncthreads();

    for (int t = 1; t < TT; t++) {
        float e = e_next;
        if (t + 1 < TT) e_next = Erow[(t + 1) * NN + j];   // prefetch next row

        // matvec: S = sum_i p_i * A[i][j], 8 rotating half2 accumulators
        __half2 acc[8];
#pragma unroll
        for (int i = 0; i < 8; i++) acc[i] = __float2half2_rn(0.f);
        const float4* p4 = reinterpret_cast<const float4*>(psm);
#pragma unroll
        for (int q = 0; q < 32; q++) {
            float4 v = p4[q];                               // broadcast LDS.128 (8 halves)
            const __half2* pv = reinterpret_cast<const __half2*>(&v);
            acc[(4 * q + 0) & 7] = __hfma2(a[4 * q + 0], pv[0], acc[(4 * q + 0) & 7]);
            acc[(4 * q + 1) & 7] = __hfma2(a[4 * q + 1], pv[1], acc[(4 * q + 1) & 7]);
            acc[(4 * q + 2) & 7] = __hfma2(a[4 * q + 2], pv[2], acc[(4 * q + 2) & 7]);
            acc[(4 * q + 3) & 7] = __hfma2(a[4 * q + 3], pv[3], acc[(4 * q + 3) & 7]);
        }
        float S = 0.f;
#pragma unroll
        for (int i = 0; i < 8; i++) {
            float2 f = __half22float2(acc[i]);
            S += f.x + f.y;
        }

        float na = e + mprev + __logf(S);

        // block max of na
        float mm = na;
#pragma unroll
        for (int o = 16; o; o >>= 1) mm = fmaxf(mm, __shfl_xor_sync(0xffffffffu, mm, o));
        if (lane == 0) red[wid] = mm;
        __syncthreads();                                    // also fences matvec reads of psm
        float mnew = red[0];
#pragma unroll
        for (int w = 1; w < 8; w++) mnew = fmaxf(mnew, red[w]);

        p = __expf(na - mnew);
        psm[j] = __float2half(p);
        mprev = mnew;
        __syncthreads();                                    // psm ready for next step
    }

    // log_prop[b] = mprev + log(sum_j p_j)
    float s = p;
#pragma unroll
    for (int o = 16; o; o >>= 1) s += __shfl_xor_sync(0xffffffffu, s, o);
    if (lane == 0) red[wid] = s;
    __syncthreads();
    if (j == 0) {
        float tot = 0.f;
#pragma unroll
        for (int w = 0; w < 8; w++) tot += red[w];
        logprop_g[b] = mprev + __logf(tot);
    }
}

// ---------------- final: sum log_props over batch ----------------
__global__ void finalize_kernel(float* __restrict__ out) {
    __shared__ float red[2];
    int t = threadIdx.x;                                    // 64 threads
    float v = logprop_g[t];
#pragma unroll
    for (int o = 16; o; o >>= 1) v += __shfl_xor_sync(0xffffffffu, v, o);
    if ((t & 31) == 0) red[t >> 5] = v;
    __syncthreads();
    if (t == 0) out[0] = red[0] + red[1];
}

// ---------------- launch ----------------
extern "C" void kernel_launch(void* const* d_in, const int* in_sizes, int n_in,
                              void* d_out, int out_size) {
    (void)in_sizes; (void)n_in; (void)out_size;
    const float* X     = (const float*)d_in[0];
    const float* mu    = (const float*)d_in[1];
    const float* lv    = (const float*)d_in[2];
    const float* trans = (const float*)d_in[3];
    const float* pri   = (const float*)d_in[4];
    float* out = (float*)d_out;

    prep_pi<<<1, 256>>>(pri);
    prep_trans<<<NN, 256>>>(trans);
    prep_packA<<<NN / 2, 256>>>();
    prep_W<<<(NN * DD) / 256, 256>>>(mu, lv);
    prep_c<<<NN, DD>>>(mu, lv);
    emis_kernel<<<(BB * TT) / 32, 256>>>(X);
    forward_rec<<<BB, 256>>>();
    finalize_kernel<<<1, 64>>>(out);
}